// round 5
// baseline (speedup 1.0000x reference)
#include <cuda_runtime.h>
#include <math.h>

#define NB_MOL 128
#define NA 512
#define NF 64
#define CO 14.399645478425668f
#define SQRT_PI 1.7724538509055159f

// ---------------- scratch (device globals; no allocation allowed) ----------
__device__ float g_C[(size_t)NB_MOL * NA * NA];   // 134 MB: per-molecule matrix / Cholesky factor
__device__ float g_chi[NB_MOL * NA];

// ---------------- chi = feats @ w  ----------------------------------------
__global__ void __launch_bounds__(256) chi_kernel(const float* __restrict__ feats,
                                                  const float* __restrict__ w) {
    int a    = blockIdx.x * 8 + (threadIdx.x >> 5);
    int lane = threadIdx.x & 31;
    float v = feats[(size_t)a * NF + lane]      * w[lane]
            + feats[(size_t)a * NF + lane + 32] * w[lane + 32];
#pragma unroll
    for (int off = 16; off; off >>= 1) v += __shfl_down_sync(0xffffffffu, v, off);
    if (lane == 0) g_chi[a] = v;
}

// ---------------- build C (full square; only lower+diag consumed) ----------
__global__ void __launch_bounds__(256) build_kernel(const float* __restrict__ pos,
                                                    const int*   __restrict__ atype,
                                                    const float* __restrict__ hard,
                                                    const float* __restrict__ sigma) {
    __shared__ float sx[NA], sy[NA], sz[NA], s2[NA], sdg[NA];
    int m   = blockIdx.y;
    int rb  = blockIdx.x * 32;
    int tid = threadIdx.x;
    for (int i = tid; i < NA; i += 256) {
        int g = m * NA + i;
        sx[i] = pos[3 * g];  sy[i] = pos[3 * g + 1];  sz[i] = pos[3 * g + 2];
        int sp = atype[g];
        float sg = sigma[sp];
        s2[i]  = sg * sg;
        sdg[i] = hard[sp] * hard[sp] + CO / (SQRT_PI * sg);
    }
    __syncthreads();
    float* C = g_C + (size_t)m * NA * NA;
    for (int k = 0; k < 64; ++k) {
        int idx = tid + k * 256;
        int il  = idx >> 9;
        int j   = idx & (NA - 1);
        int i   = rb + il;
        float val;
        if (i == j) {
            val = sdg[i];
        } else {
            float dx = sx[i] - sx[j], dy = sy[i] - sy[j], dz = sz[i] - sz[j];
            float d2 = dx * dx + dy * dy + dz * dz;
            float d  = sqrtf(d2);
            val = CO * erff(d / sqrtf(2.f * (s2[i] + s2[j]))) / d;
        }
        C[(size_t)i * NA + j] = val;
    }
}

// ---------------- blocked Cholesky (NB=32), one CTA per molecule -----------
#define MAXM 480
#define CHO_SHMEM ((MAXM * 33 + 32 * 33 + 32) * 4)

extern __shared__ float cho_sh[];

__global__ void __launch_bounds__(256) cholesky_kernel() {
    float* s_P   = cho_sh;                 // [MAXM][33] panel (padded vs bank conflicts)
    float* s_D   = cho_sh + MAXM * 33;     // [32][33]  diag block
    float* s_inv = s_D + 32 * 33;          // [32]      1/L[t][t]
    int m    = blockIdx.x;
    float* C = g_C + (size_t)m * NA * NA;
    int tid = threadIdx.x, lane = tid & 31, wid = tid >> 5;

    for (int kb = 0; kb < NA / 32; ++kb) {
        int k0 = kb * 32;
        int M  = NA - k0 - 32;             // trailing size (multiple of 32)

        // --- load diag block ---
        for (int t = tid; t < 1024; t += 256) {
            int i = t >> 5, j = t & 31;
            s_D[i * 33 + j] = C[(size_t)(k0 + i) * NA + k0 + j];
        }
        __syncthreads();

        // --- factor 32x32 (warp 0, lane = row) ---
        if (wid == 0) {
            for (int k = 0; k < 32; ++k) {
                if (lane == k) {
                    float s = sqrtf(s_D[k * 33 + k]);
                    s_D[k * 33 + k] = s;
                    s_inv[k] = 1.0f / s;
                }
                __syncwarp();
                if (lane > k) s_D[lane * 33 + k] *= s_inv[k];
                __syncwarp();
                if (lane > k) {
                    float lik = s_D[lane * 33 + k];
                    for (int j = k + 1; j <= lane; ++j)
                        s_D[lane * 33 + j] -= lik * s_D[j * 33 + k];
                }
                __syncwarp();
            }
        }
        __syncthreads();

        // --- write diag block back ---
        for (int t = tid; t < 1024; t += 256) {
            int i = t >> 5, j = t & 31;
            C[(size_t)(k0 + i) * NA + k0 + j] = s_D[i * 33 + j];
        }

        // --- panel solve L21 * L11^T = A21 (thread per row) ---
        for (int r = tid; r < M; r += 256) {
            size_t rowb = (size_t)(k0 + 32 + r) * NA + k0;
            float a[32];
#pragma unroll
            for (int t = 0; t < 8; ++t) {
                float4 v = *(const float4*)(C + rowb + 4 * t);
                a[4 * t] = v.x; a[4 * t + 1] = v.y; a[4 * t + 2] = v.z; a[4 * t + 3] = v.w;
            }
#pragma unroll
            for (int t = 0; t < 32; ++t) {
                a[t] *= s_inv[t];
                float xv = a[t];
#pragma unroll
                for (int j = t + 1; j < 32; ++j)
                    a[j] -= xv * s_D[j * 33 + t];
            }
#pragma unroll
            for (int t = 0; t < 8; ++t)
                *(float4*)(C + rowb + 4 * t) = make_float4(a[4 * t], a[4 * t + 1], a[4 * t + 2], a[4 * t + 3]);
#pragma unroll
            for (int t = 0; t < 32; ++t) s_P[r * 33 + t] = a[t];
        }
        __syncthreads();

        // --- trailing SYRK: A22 -= P P^T (64x32 warp tiles, 2 rows/lane) ---
        if (M > 0) {
            int RT = (M + 63) >> 6;
            int CT = M >> 5;
            int cnt = 0;
            for (int bi = 0; bi < RT; ++bi) {
                int bjmax = min(2 * bi + 1, CT - 1);
                for (int bj = 0; bj <= bjmax; ++bj, ++cnt) {
                    if ((cnt & 7) != wid) continue;
                    int r1 = bi * 64 + lane, r2 = r1 + 32;
                    int cb = bj * 32;
                    bool v1 = r1 < M, v2 = r2 < M;
                    float acc0[32], acc1[32];
#pragma unroll
                    for (int c = 0; c < 32; ++c) { acc0[c] = 0.f; acc1[c] = 0.f; }
#pragma unroll 8
                    for (int t = 0; t < 32; ++t) {
                        float a0 = v1 ? s_P[r1 * 33 + t] : 0.f;
                        float a1 = v2 ? s_P[r2 * 33 + t] : 0.f;
#pragma unroll
                        for (int c = 0; c < 32; ++c) {
                            float pc = s_P[(cb + c) * 33 + t];
                            acc0[c] += a0 * pc;
                            acc1[c] += a1 * pc;
                        }
                    }
                    if (v1) {
                        size_t rbp = (size_t)(k0 + 32 + r1) * NA + k0 + 32 + cb;
#pragma unroll
                        for (int c4 = 0; c4 < 8; ++c4) {
                            float4 v = *(float4*)(C + rbp + 4 * c4);
                            v.x -= acc0[4 * c4];     v.y -= acc0[4 * c4 + 1];
                            v.z -= acc0[4 * c4 + 2]; v.w -= acc0[4 * c4 + 3];
                            *(float4*)(C + rbp + 4 * c4) = v;
                        }
                    }
                    if (v2) {
                        size_t rbp = (size_t)(k0 + 32 + r2) * NA + k0 + 32 + cb;
#pragma unroll
                        for (int c4 = 0; c4 < 8; ++c4) {
                            float4 v = *(float4*)(C + rbp + 4 * c4);
                            v.x -= acc1[4 * c4];     v.y -= acc1[4 * c4 + 1];
                            v.z -= acc1[4 * c4 + 2]; v.w -= acc1[4 * c4 + 3];
                            *(float4*)(C + rbp + 4 * c4) = v;
                        }
                    }
                }
            }
        }
        __syncthreads();
    }
}

// ---------------- 2-RHS fwd/bwd triangular solves + Schur combine ----------
__global__ void __launch_bounds__(256) trsv_kernel(const float* __restrict__ tc,
                                                   float* __restrict__ out) {
    __shared__ float s_b0[NA], s_b1[NA];
    __shared__ float s_D[32 * 33];
    __shared__ float s_red[16];
    __shared__ float s_lam;
    int m = blockIdx.x;
    const float* C = g_C + (size_t)m * NA * NA;
    int tid = threadIdx.x, lane = tid & 31, wid = tid >> 5;

    for (int i = tid; i < NA; i += 256) {
        s_b0[i] = -g_chi[m * NA + i];
        s_b1[i] = 1.0f;
    }
    __syncthreads();

    // forward: L z = b
    for (int kb = 0; kb < NA / 32; ++kb) {
        int k0 = kb * 32;
        for (int t = tid; t < 1024; t += 256) {
            int i = t >> 5, j = t & 31;
            s_D[i * 33 + j] = C[(size_t)(k0 + i) * NA + k0 + j];
        }
        __syncthreads();
        if (wid == 0) {
            float a0 = s_b0[k0 + lane], a1 = s_b1[k0 + lane];
            for (int t = 0; t < 32; ++t) {
                float dtt = s_D[t * 33 + t];
                float v0 = __shfl_sync(0xffffffffu, a0, t) / dtt;
                float v1 = __shfl_sync(0xffffffffu, a1, t) / dtt;
                if (lane == t) { s_b0[k0 + t] = v0; s_b1[k0 + t] = v1; }
                if (lane > t) {
                    float l = s_D[lane * 33 + t];
                    a0 -= l * v0; a1 -= l * v1;
                }
            }
        }
        __syncthreads();
        for (int rbase = k0 + 32; rbase < NA; rbase += 32) {
            int row = rbase + (tid >> 3);
            int g   = tid & 7;
            float p0 = 0.f, p1 = 0.f;
            const float* rp = C + (size_t)row * NA + k0;
#pragma unroll
            for (int mm = 0; mm < 4; ++mm) {
                int jj = g + 8 * mm;
                float l = rp[jj];
                p0 += l * s_b0[k0 + jj];
                p1 += l * s_b1[k0 + jj];
            }
#pragma unroll
            for (int off = 4; off; off >>= 1) {
                p0 += __shfl_down_sync(0xffffffffu, p0, off);
                p1 += __shfl_down_sync(0xffffffffu, p1, off);
            }
            if (g == 0) { s_b0[row] -= p0; s_b1[row] -= p1; }
        }
        __syncthreads();
    }

    // backward: L^T y = z
    for (int kb = NA / 32 - 1; kb >= 0; --kb) {
        int k0 = kb * 32;
        for (int t = tid; t < 1024; t += 256) {
            int i = t >> 5, j = t & 31;
            s_D[i * 33 + j] = C[(size_t)(k0 + i) * NA + k0 + j];
        }
        __syncthreads();
        if (wid == 0) {
            float a0 = s_b0[k0 + lane], a1 = s_b1[k0 + lane];
            for (int t = 31; t >= 0; --t) {
                float dtt = s_D[t * 33 + t];
                float v0 = __shfl_sync(0xffffffffu, a0, t) / dtt;
                float v1 = __shfl_sync(0xffffffffu, a1, t) / dtt;
                if (lane == t) { s_b0[k0 + t] = v0; s_b1[k0 + t] = v1; }
                if (lane < t) {
                    float l = s_D[t * 33 + lane];
                    a0 -= l * v0; a1 -= l * v1;
                }
            }
        }
        __syncthreads();
        for (int j = tid; j < k0; j += 256) {
            float a0 = s_b0[j], a1 = s_b1[j];
#pragma unroll 8
            for (int t = 0; t < 32; ++t) {
                float l  = C[(size_t)(k0 + t) * NA + j];
                float x0 = s_b0[k0 + t], x1 = s_b1[k0 + t];
                a0 -= l * x0; a1 -= l * x1;
            }
            s_b0[j] = a0; s_b1[j] = a1;
        }
        __syncthreads();
    }

    // lambda + q
    float l0 = 0.f, l1 = 0.f;
    for (int i = tid; i < NA; i += 256) { l0 += s_b0[i]; l1 += s_b1[i]; }
#pragma unroll
    for (int off = 16; off; off >>= 1) {
        l0 += __shfl_down_sync(0xffffffffu, l0, off);
        l1 += __shfl_down_sync(0xffffffffu, l1, off);
    }
    if (lane == 0) { s_red[wid] = l0; s_red[8 + wid] = l1; }
    __syncthreads();
    if (tid == 0) {
        float S1 = 0.f, S2 = 0.f;
        for (int w = 0; w < 8; ++w) { S1 += s_red[w]; S2 += s_red[8 + w]; }
        s_lam = (S1 - tc[m]) / S2;
    }
    __syncthreads();
    float lam = s_lam;
    for (int i = tid; i < NA; i += 256)
        out[NB_MOL + m * NA + i] = s_b0[i] - lam * s_b1[i];
}

// ---------------- energy: e = 0.5 q^T C q + chi.q (recomputed entries) -----
__global__ void __launch_bounds__(512) energy_kernel(const float* __restrict__ pos,
                                                     const int*   __restrict__ atype,
                                                     const float* __restrict__ hard,
                                                     const float* __restrict__ sigma,
                                                     float* __restrict__ out) {
    __shared__ float sx[NA], sy[NA], sz[NA], s2[NA], sdg[NA], sq[NA], sch[NA];
    __shared__ float s_red[16];
    int m = blockIdx.x, tid = threadIdx.x;
    {
        int g = m * NA + tid;
        sx[tid] = pos[3 * g]; sy[tid] = pos[3 * g + 1]; sz[tid] = pos[3 * g + 2];
        int sp = atype[g];
        float sg = sigma[sp];
        s2[tid]  = sg * sg;
        sdg[tid] = hard[sp] * hard[sp] + CO / (SQRT_PI * sg);
        sq[tid]  = out[NB_MOL + m * NA + tid];
        sch[tid] = g_chi[m * NA + tid];
    }
    __syncthreads();
    int i = tid;
    float xi = sx[i], yi = sy[i], zi = sz[i], si2 = s2[i];
    float z = sdg[i] * sq[i];
    for (int j = 0; j < NA; ++j) {
        if (j == i) continue;
        float dx = xi - sx[j], dy = yi - sy[j], dz = zi - sz[j];
        float d2 = dx * dx + dy * dy + dz * dz;
        float d  = sqrtf(d2);
        float v  = CO * erff(d / sqrtf(2.f * (si2 + s2[j]))) / d;
        z += v * sq[j];
    }
    float e = (0.5f * z + sch[i]) * sq[i];
#pragma unroll
    for (int off = 16; off; off >>= 1) e += __shfl_down_sync(0xffffffffu, e, off);
    int lane = tid & 31, wid = tid >> 5;
    if (lane == 0) s_red[wid] = e;
    __syncthreads();
    if (tid == 0) {
        float s = 0.f;
        for (int w = 0; w < 16; ++w) s += s_red[w];
        out[m] = s;
    }
}

// ---------------- launch ----------------------------------------------------
extern "C" void kernel_launch(void* const* d_in, const int* in_sizes, int n_in,
                              void* d_out, int out_size) {
    const float* feats = (const float*)d_in[0];   // (N, 64)
    const float* pos   = (const float*)d_in[1];   // (N, 3)
    const int*   atype = (const int*)  d_in[2];   // (N,)
    const float* tc    = (const float*)d_in[3];   // (B, 1)
    const float* w     = (const float*)d_in[4];   // (64, 1)
    const float* hard  = (const float*)d_in[5];   // (4,)
    const float* sigma = (const float*)d_in[6];   // (4,)
    float* out = (float*)d_out;                   // [B e | N q]

    (void)in_sizes; (void)n_in; (void)out_size;

    chi_kernel<<<NB_MOL * NA / 8, 256>>>(feats, w);
    build_kernel<<<dim3(16, NB_MOL), 256>>>(pos, atype, hard, sigma);
    cudaFuncSetAttribute(cholesky_kernel, cudaFuncAttributeMaxDynamicSharedMemorySize, CHO_SHMEM);
    cholesky_kernel<<<NB_MOL, 256, CHO_SHMEM>>>();
    trsv_kernel<<<NB_MOL, 256>>>(tc, out);
    energy_kernel<<<NB_MOL, 512>>>(pos, atype, hard, sigma, out);
}

// round 6
// speedup vs baseline: 1.2303x; 1.2303x over previous
#include <cuda_runtime.h>
#include <math.h>

#define NB_MOL 128
#define NA 512
#define NF 64
#define CO 14.399645478425668f
#define SQRT_PI 1.7724538509055159f

// ---------------- scratch (device globals; no allocation allowed) ----------
__device__ float g_C[(size_t)NB_MOL * NA * NA];   // 134 MB: matrix / Cholesky factor (lower)
__device__ float g_chi[NB_MOL * NA];
__device__ float g_dinv[NB_MOL * NA];             // 1/L[i][i]

// ---------------- chi = feats @ w  ----------------------------------------
__global__ void __launch_bounds__(256) chi_kernel(const float* __restrict__ feats,
                                                  const float* __restrict__ w) {
    int a    = blockIdx.x * 8 + (threadIdx.x >> 5);
    int lane = threadIdx.x & 31;
    float v = feats[(size_t)a * NF + lane]      * w[lane]
            + feats[(size_t)a * NF + lane + 32] * w[lane + 32];
#pragma unroll
    for (int off = 16; off; off >>= 1) v += __shfl_down_sync(0xffffffffu, v, off);
    if (lane == 0) g_chi[a] = v;
}

// ---------------- build C, LOWER TRIANGLE ONLY -----------------------------
__global__ void __launch_bounds__(256) build_kernel(const float* __restrict__ pos,
                                                    const int*   __restrict__ atype,
                                                    const float* __restrict__ hard,
                                                    const float* __restrict__ sigma) {
    __shared__ float sx[NA], sy[NA], sz[NA], s2[NA], sdg[NA];
    int m   = blockIdx.y;
    int rb  = blockIdx.x * 32;
    int tid = threadIdx.x;
    for (int i = tid; i < NA; i += 256) {
        int g = m * NA + i;
        sx[i] = pos[3 * g];  sy[i] = pos[3 * g + 1];  sz[i] = pos[3 * g + 2];
        int sp = atype[g];
        float sg = sigma[sp];
        s2[i]  = sg * sg;
        sdg[i] = hard[sp] * hard[sp] + CO / (SQRT_PI * sg);
    }
    __syncthreads();
    float* C = g_C + (size_t)m * NA * NA;
    int ncol = rb + 32;                    // cols 0 .. rb+31 (covers lower+diag block)
    for (int il = 0; il < 32; ++il) {
        int i = rb + il;
        float xi = sx[i], yi = sy[i], zi = sz[i], si2 = s2[i];
        for (int j = tid; j < ncol; j += 256) {
            float val;
            if (j == i) {
                val = sdg[i];
            } else {
                float dx = xi - sx[j], dy = yi - sy[j], dz = zi - sz[j];
                float d2 = dx * dx + dy * dy + dz * dz;
                float d  = sqrtf(d2);
                val = CO * erff(d / sqrtf(2.f * (si2 + s2[j]))) / d;
            }
            C[(size_t)i * NA + j] = val;
        }
    }
}

// ---------------- blocked Cholesky (NB=32), one CTA per molecule -----------
#define PS 480                                  // transposed panel stride
#define CHO_SHMEM ((32 * PS + 32 * 33 + 32) * 4)

extern __shared__ float cho_sh[];

__global__ void __launch_bounds__(512) cholesky_kernel() {
    float* s_Pt  = cho_sh;                 // [32][PS]  transposed panel
    float* s_D   = cho_sh + 32 * PS;       // [32][33]  diag block
    float* s_inv = s_D + 32 * 33;          // [32]      1/L[t][t]
    int m    = blockIdx.x;
    float* C = g_C + (size_t)m * NA * NA;
    int tid = threadIdx.x, lane = tid & 31, wid = tid >> 5;

    for (int kb = 0; kb < NA / 32; ++kb) {
        int k0 = kb * 32;
        int M  = NA - k0 - 32;

        // --- load diag block ---
        for (int t = tid; t < 1024; t += 512) {
            int i = t >> 5, j = t & 31;
            s_D[i * 33 + j] = C[(size_t)(k0 + i) * NA + k0 + j];
        }
        __syncthreads();

        // --- factor 32x32 (warp 0, lane = row) ---
        if (wid == 0) {
            for (int k = 0; k < 32; ++k) {
                if (lane == k) {
                    float s = sqrtf(s_D[k * 33 + k]);
                    s_D[k * 33 + k] = s;
                    s_inv[k] = 1.0f / s;
                }
                __syncwarp();
                if (lane > k) s_D[lane * 33 + k] *= s_inv[k];
                __syncwarp();
                if (lane > k) {
                    float lik = s_D[lane * 33 + k];
                    for (int j = k + 1; j <= lane; ++j)
                        s_D[lane * 33 + j] -= lik * s_D[j * 33 + k];
                }
                __syncwarp();
            }
            g_dinv[(size_t)m * NA + k0 + lane] = s_inv[lane];
        }
        __syncthreads();

        // --- write diag block back ---
        for (int t = tid; t < 1024; t += 512) {
            int i = t >> 5, j = t & 31;
            C[(size_t)(k0 + i) * NA + k0 + j] = s_D[i * 33 + j];
        }

        // --- panel solve L21 * L11^T = A21 (thread per row; one wave) ---
        for (int r = tid; r < M; r += 512) {
            size_t rowb = (size_t)(k0 + 32 + r) * NA + k0;
            float a[32];
#pragma unroll
            for (int t = 0; t < 8; ++t) {
                float4 v = *(const float4*)(C + rowb + 4 * t);
                a[4 * t] = v.x; a[4 * t + 1] = v.y; a[4 * t + 2] = v.z; a[4 * t + 3] = v.w;
            }
#pragma unroll
            for (int t = 0; t < 32; ++t) {
                a[t] *= s_inv[t];
                float xv = a[t];
#pragma unroll
                for (int j = t + 1; j < 32; ++j)
                    a[j] -= xv * s_D[j * 33 + t];
            }
#pragma unroll
            for (int t = 0; t < 8; ++t)
                *(float4*)(C + rowb + 4 * t) = make_float4(a[4 * t], a[4 * t + 1], a[4 * t + 2], a[4 * t + 3]);
#pragma unroll
            for (int t = 0; t < 32; ++t) s_Pt[t * PS + r] = a[t];   // transposed
        }
        __syncthreads();

        // --- trailing SYRK: A22 -= P P^T (64x32 warp tiles, 2 rows/lane) ---
        if (M > 0) {
            int RT = (M + 63) >> 6;
            int CT = M >> 5;
            int cnt = 0;
            for (int bi = 0; bi < RT; ++bi) {
                int bjmax = min(2 * bi + 1, CT - 1);
                for (int bj = 0; bj <= bjmax; ++bj, ++cnt) {
                    if ((cnt & 15) != wid) continue;
                    int r1 = bi * 64 + lane, r2 = r1 + 32;
                    int cb = bj * 32;
                    bool v1 = r1 < M, v2 = r2 < M;
                    float acc0[32], acc1[32];
#pragma unroll
                    for (int c = 0; c < 32; ++c) { acc0[c] = 0.f; acc1[c] = 0.f; }
#pragma unroll 4
                    for (int t = 0; t < 32; ++t) {
                        float a0 = v1 ? s_Pt[t * PS + r1] : 0.f;
                        float a1 = v2 ? s_Pt[t * PS + r2] : 0.f;
                        const float4* pp = (const float4*)&s_Pt[t * PS + cb];
#pragma unroll
                        for (int c4 = 0; c4 < 8; ++c4) {
                            float4 p = pp[c4];
                            acc0[4 * c4]     += a0 * p.x;
                            acc0[4 * c4 + 1] += a0 * p.y;
                            acc0[4 * c4 + 2] += a0 * p.z;
                            acc0[4 * c4 + 3] += a0 * p.w;
                            acc1[4 * c4]     += a1 * p.x;
                            acc1[4 * c4 + 1] += a1 * p.y;
                            acc1[4 * c4 + 2] += a1 * p.z;
                            acc1[4 * c4 + 3] += a1 * p.w;
                        }
                    }
                    if (v1) {
                        size_t rbp = (size_t)(k0 + 32 + r1) * NA + k0 + 32 + cb;
#pragma unroll
                        for (int c4 = 0; c4 < 8; ++c4) {
                            float4 v = *(float4*)(C + rbp + 4 * c4);
                            v.x -= acc0[4 * c4];     v.y -= acc0[4 * c4 + 1];
                            v.z -= acc0[4 * c4 + 2]; v.w -= acc0[4 * c4 + 3];
                            *(float4*)(C + rbp + 4 * c4) = v;
                        }
                    }
                    if (v2) {
                        size_t rbp = (size_t)(k0 + 32 + r2) * NA + k0 + 32 + cb;
#pragma unroll
                        for (int c4 = 0; c4 < 8; ++c4) {
                            float4 v = *(float4*)(C + rbp + 4 * c4);
                            v.x -= acc1[4 * c4];     v.y -= acc1[4 * c4 + 1];
                            v.z -= acc1[4 * c4 + 2]; v.w -= acc1[4 * c4 + 3];
                            *(float4*)(C + rbp + 4 * c4) = v;
                        }
                    }
                }
            }
        }
        __syncthreads();
    }
}

// ------- 2-RHS fwd/bwd triangular solves + Schur combine + energy ----------
__global__ void __launch_bounds__(1024) trsv_kernel(const float* __restrict__ tc,
                                                    float* __restrict__ out) {
    __shared__ float s_b0[NA], s_b1[NA];
    __shared__ float s_D[32 * 33];
    __shared__ float s_iv[32];
    __shared__ float s_red[64];
    __shared__ float s_lam;
    int m = blockIdx.x;
    const float* C    = g_C    + (size_t)m * NA * NA;
    const float* dinv = g_dinv + (size_t)m * NA;
    int tid = threadIdx.x, lane = tid & 31, wid = tid >> 5;

    for (int i = tid; i < NA; i += 1024) {
        s_b0[i] = -g_chi[m * NA + i];
        s_b1[i] = 1.0f;
    }
    __syncthreads();

    // forward: L z = b
    for (int kb = 0; kb < NA / 32; ++kb) {
        int k0 = kb * 32;
        {
            int i = tid >> 5, j = tid & 31;
            s_D[i * 33 + j] = C[(size_t)(k0 + i) * NA + k0 + j];
        }
        if (tid < 32) s_iv[tid] = dinv[k0 + tid];
        __syncthreads();
        if (wid == 0) {
            float a0 = s_b0[k0 + lane], a1 = s_b1[k0 + lane];
            for (int t = 0; t < 32; ++t) {
                float iv = s_iv[t];
                float v0 = __shfl_sync(0xffffffffu, a0, t) * iv;
                float v1 = __shfl_sync(0xffffffffu, a1, t) * iv;
                if (lane == t) { s_b0[k0 + t] = v0; s_b1[k0 + t] = v1; }
                if (lane > t) {
                    float l = s_D[lane * 33 + t];
                    a0 -= l * v0; a1 -= l * v1;
                }
            }
        }
        __syncthreads();
        int M = NA - k0 - 32;
        int g = tid & 7;
        float4 b0v = *(const float4*)(s_b0 + k0 + 4 * g);
        float4 b1v = *(const float4*)(s_b1 + k0 + 4 * g);
        for (int rw = (tid >> 3); rw < M; rw += 128) {
            int row = k0 + 32 + rw;
            float4 lv = *(const float4*)(C + (size_t)row * NA + k0 + 4 * g);
            float p0 = lv.x * b0v.x + lv.y * b0v.y + lv.z * b0v.z + lv.w * b0v.w;
            float p1 = lv.x * b1v.x + lv.y * b1v.y + lv.z * b1v.z + lv.w * b1v.w;
#pragma unroll
            for (int off = 4; off; off >>= 1) {
                p0 += __shfl_down_sync(0xffffffffu, p0, off, 8);
                p1 += __shfl_down_sync(0xffffffffu, p1, off, 8);
            }
            if (g == 0) { s_b0[row] -= p0; s_b1[row] -= p1; }
        }
        __syncthreads();
    }

    // backward: L^T y = z
    for (int kb = NA / 32 - 1; kb >= 0; --kb) {
        int k0 = kb * 32;
        {
            int i = tid >> 5, j = tid & 31;
            s_D[i * 33 + j] = C[(size_t)(k0 + i) * NA + k0 + j];
        }
        if (tid < 32) s_iv[tid] = dinv[k0 + tid];
        __syncthreads();
        if (wid == 0) {
            float a0 = s_b0[k0 + lane], a1 = s_b1[k0 + lane];
            for (int t = 31; t >= 0; --t) {
                float iv = s_iv[t];
                float v0 = __shfl_sync(0xffffffffu, a0, t) * iv;
                float v1 = __shfl_sync(0xffffffffu, a1, t) * iv;
                if (lane == t) { s_b0[k0 + t] = v0; s_b1[k0 + t] = v1; }
                if (lane < t) {
                    float l = s_D[t * 33 + lane];
                    a0 -= l * v0; a1 -= l * v1;
                }
            }
        }
        __syncthreads();
        for (int j = tid; j < k0; j += 1024) {
            float a0 = s_b0[j], a1 = s_b1[j];
#pragma unroll 8
            for (int t = 0; t < 32; ++t) {
                float l  = C[(size_t)(k0 + t) * NA + j];
                float x0 = s_b0[k0 + t], x1 = s_b1[k0 + t];
                a0 -= l * x0; a1 -= l * x1;
            }
            s_b0[j] = a0; s_b1[j] = a1;
        }
        __syncthreads();
    }

    // lambda
    float l0 = 0.f, l1 = 0.f;
    for (int i = tid; i < NA; i += 1024) { l0 += s_b0[i]; l1 += s_b1[i]; }
#pragma unroll
    for (int off = 16; off; off >>= 1) {
        l0 += __shfl_down_sync(0xffffffffu, l0, off);
        l1 += __shfl_down_sync(0xffffffffu, l1, off);
    }
    if (lane == 0) { s_red[wid] = l0; s_red[32 + wid] = l1; }
    __syncthreads();
    if (tid == 0) {
        float S1 = 0.f, S2 = 0.f;
        for (int w = 0; w < 32; ++w) { S1 += s_red[w]; S2 += s_red[32 + w]; }
        s_lam = (S1 - tc[m]) / S2;
    }
    __syncthreads();
    float lam = s_lam;

    // q output + energy: e = 0.5 * (chi.q - lam * Q)   [exact KKT identity]
    float ep = 0.f;
    for (int i = tid; i < NA; i += 1024) {
        float q = s_b0[i] - lam * s_b1[i];
        out[NB_MOL + m * NA + i] = q;
        ep += g_chi[m * NA + i] * q;
    }
#pragma unroll
    for (int off = 16; off; off >>= 1) ep += __shfl_down_sync(0xffffffffu, ep, off);
    if (lane == 0) s_red[wid] = ep;
    __syncthreads();
    if (tid == 0) {
        float s = 0.f;
        for (int w = 0; w < 32; ++w) s += s_red[w];
        out[m] = 0.5f * (s - lam * tc[m]);
    }
}

// ---------------- launch ----------------------------------------------------
extern "C" void kernel_launch(void* const* d_in, const int* in_sizes, int n_in,
                              void* d_out, int out_size) {
    const float* feats = (const float*)d_in[0];   // (N, 64)
    const float* pos   = (const float*)d_in[1];   // (N, 3)
    const int*   atype = (const int*)  d_in[2];   // (N,)
    const float* tc    = (const float*)d_in[3];   // (B, 1)
    const float* w     = (const float*)d_in[4];   // (64, 1)
    const float* hard  = (const float*)d_in[5];   // (4,)
    const float* sigma = (const float*)d_in[6];   // (4,)
    float* out = (float*)d_out;                   // [B e | N q]

    (void)in_sizes; (void)n_in; (void)out_size;

    chi_kernel<<<NB_MOL * NA / 8, 256>>>(feats, w);
    build_kernel<<<dim3(16, NB_MOL), 256>>>(pos, atype, hard, sigma);
    cudaFuncSetAttribute(cholesky_kernel, cudaFuncAttributeMaxDynamicSharedMemorySize, CHO_SHMEM);
    cholesky_kernel<<<NB_MOL, 512, CHO_SHMEM>>>();
    trsv_kernel<<<NB_MOL, 1024>>>(tc, out);
}

// round 7
// speedup vs baseline: 1.5873x; 1.2902x over previous
#include <cuda_runtime.h>
#include <math.h>

#define NB_MOL 128
#define NA 512
#define NF 64
#define CO 14.399645478425668f
#define SQRT_PI 1.7724538509055159f
#define PS 480

typedef unsigned long long u64;

// ---------------- scratch (device globals; no allocation allowed) ----------
__device__ float g_C[(size_t)NB_MOL * NA * NA];   // matrix / Cholesky factor (lower)
__device__ float g_chi[NB_MOL * NA];

// ---------------- packed fp32x2 helpers (sm_103a FFMA2 path) ---------------
__device__ __forceinline__ void ffma2(u64& acc, u64 a, u64 b) {
    asm("fma.rn.f32x2 %0, %1, %2, %0;" : "+l"(acc) : "l"(a), "l"(b));
}
__device__ __forceinline__ u64 fmul2(u64 a, u64 b) {
    u64 r; asm("mul.rn.f32x2 %0, %1, %2;" : "=l"(r) : "l"(a), "l"(b)); return r;
}
__device__ __forceinline__ u64 fadd2(u64 a, u64 b) {
    u64 r; asm("add.rn.f32x2 %0, %1, %2;" : "=l"(r) : "l"(a), "l"(b)); return r;
}
__device__ __forceinline__ u64 splat2(float x) {
    u64 r; asm("mov.b64 %0, {%1, %1};" : "=l"(r) : "f"(x)); return r;
}
__device__ __forceinline__ u64 nsplat2(float x) {
    float nx = -x;
    u64 r; asm("mov.b64 %0, {%1, %1};" : "=l"(r) : "f"(nx)); return r;
}
__device__ __forceinline__ u64 pack2(float lo, float hi) {
    u64 r; asm("mov.b64 %0, {%1, %2};" : "=l"(r) : "f"(lo), "f"(hi)); return r;
}
__device__ __forceinline__ void unpack2(u64 v, float& lo, float& hi) {
    asm("mov.b64 {%0, %1}, %2;" : "=f"(lo), "=f"(hi) : "l"(v));
}

// ---------------- chi = feats @ w  ----------------------------------------
__global__ void __launch_bounds__(256) chi_kernel(const float* __restrict__ feats,
                                                  const float* __restrict__ w) {
    int a    = blockIdx.x * 8 + (threadIdx.x >> 5);
    int lane = threadIdx.x & 31;
    float v = feats[(size_t)a * NF + lane]      * w[lane]
            + feats[(size_t)a * NF + lane + 32] * w[lane + 32];
#pragma unroll
    for (int off = 16; off; off >>= 1) v += __shfl_down_sync(0xffffffffu, v, off);
    if (lane == 0) g_chi[a] = v;
}

// ---------------- build C, LOWER TRIANGLE ONLY -----------------------------
__global__ void __launch_bounds__(256) build_kernel(const float* __restrict__ pos,
                                                    const int*   __restrict__ atype,
                                                    const float* __restrict__ hard,
                                                    const float* __restrict__ sigma) {
    __shared__ float sx[NA], sy[NA], sz[NA], s2[NA], sdg[NA];
    int m   = blockIdx.y;
    int rb  = blockIdx.x * 32;
    int tid = threadIdx.x;
    for (int i = tid; i < NA; i += 256) {
        int g = m * NA + i;
        sx[i] = pos[3 * g];  sy[i] = pos[3 * g + 1];  sz[i] = pos[3 * g + 2];
        int sp = atype[g];
        float sg = sigma[sp];
        s2[i]  = sg * sg;
        sdg[i] = hard[sp] * hard[sp] + CO / (SQRT_PI * sg);
    }
    __syncthreads();
    float* C = g_C + (size_t)m * NA * NA;
    int ncol = rb + 32;
    for (int il = 0; il < 32; ++il) {
        int i = rb + il;
        float xi = sx[i], yi = sy[i], zi = sz[i], si2 = s2[i];
        for (int j = tid; j < ncol; j += 256) {
            float val;
            if (j == i) {
                val = sdg[i];
            } else {
                float dx = xi - sx[j], dy = yi - sy[j], dz = zi - sz[j];
                float d2 = dx * dx + dy * dy + dz * dz;
                float d  = sqrtf(d2);
                val = CO * erff(d / sqrtf(2.f * (si2 + s2[j]))) / d;
            }
            C[(size_t)i * NA + j] = val;
        }
    }
}

// ------- fused: blocked Cholesky + fwd solve + bwd solve + outputs ---------
// shared layout (float offsets)
#define SH_PT     0                    // [32][PS] transposed panel
#define SH_D      (32 * PS)            // [32][33] diag block
#define SH_INV    (SH_D + 32 * 33)     // [32]     1/L[t][t] current block
#define SH_INVALL (SH_INV + 32)        // [512]    1/L[i][i] all
#define SH_BP     (SH_INVALL + 512)    // [512] u64 pairs (b0,b1)  (8B aligned)
#define SH_RED    (SH_BP + 1024)       // [64]
#define SH_LAM    (SH_RED + 64)
#define CHO_SHMEM ((SH_LAM + 4) * 4)

extern __shared__ float cho_sh[];

__global__ void __launch_bounds__(512) fact_solve_kernel(const float* __restrict__ tc,
                                                         float* __restrict__ out) {
    float* s_Pt     = cho_sh + SH_PT;
    float* s_D      = cho_sh + SH_D;
    float* s_inv    = cho_sh + SH_INV;
    float* s_invall = cho_sh + SH_INVALL;
    u64*   s_bp     = (u64*)(cho_sh + SH_BP);
    float* s_red    = cho_sh + SH_RED;
    float* s_lam    = cho_sh + SH_LAM;

    int m    = blockIdx.x;
    float* C = g_C + (size_t)m * NA * NA;
    int tid = threadIdx.x, lane = tid & 31, wid = tid >> 5;

    // rhs pairs: (b0, b1) = (-chi, 1)
    s_bp[tid] = pack2(-g_chi[m * NA + tid], 1.0f);
    __syncthreads();

    // =================== factorization + forward substitution ==============
    for (int kb = 0; kb < NA / 32; ++kb) {
        int k0 = kb * 32;
        int M  = NA - k0 - 32;

        // A: load diag block
        for (int t = tid; t < 1024; t += 512) {
            int i = t >> 5, j = t & 31;
            s_D[i * 33 + j] = C[(size_t)(k0 + i) * NA + k0 + j];
        }
        __syncthreads();

        // B: factor 32x32 (warp 0, lane = row)
        if (wid == 0) {
            for (int k = 0; k < 32; ++k) {
                if (lane == k) {
                    float s = sqrtf(s_D[k * 33 + k]);
                    s_D[k * 33 + k] = s;
                    s_inv[k] = 1.0f / s;
                }
                __syncwarp();
                if (lane > k) s_D[lane * 33 + k] *= s_inv[k];
                __syncwarp();
                if (lane > k) {
                    float lik = s_D[lane * 33 + k];
                    for (int j = k + 1; j <= lane; ++j)
                        s_D[lane * 33 + j] -= lik * s_D[j * 33 + k];
                }
                __syncwarp();
            }
            s_invall[k0 + lane] = s_inv[lane];
        }
        __syncthreads();

        // C: write diag back + panel solve L21 L11^T = A21 (thread per row)
        for (int t = tid; t < 1024; t += 512) {
            int i = t >> 5, j = t & 31;
            C[(size_t)(k0 + i) * NA + k0 + j] = s_D[i * 33 + j];
        }
        for (int r = tid; r < M; r += 512) {
            size_t rowb = (size_t)(k0 + 32 + r) * NA + k0;
            float a[32];
#pragma unroll
            for (int t = 0; t < 8; ++t) {
                float4 v = *(const float4*)(C + rowb + 4 * t);
                a[4 * t] = v.x; a[4 * t + 1] = v.y; a[4 * t + 2] = v.z; a[4 * t + 3] = v.w;
            }
#pragma unroll
            for (int t = 0; t < 32; ++t) {
                a[t] *= s_inv[t];
                float xv = a[t];
#pragma unroll
                for (int j = t + 1; j < 32; ++j)
                    a[j] -= xv * s_D[j * 33 + t];
            }
#pragma unroll
            for (int t = 0; t < 8; ++t)
                *(float4*)(C + rowb + 4 * t) = make_float4(a[4 * t], a[4 * t + 1], a[4 * t + 2], a[4 * t + 3]);
#pragma unroll
            for (int t = 0; t < 32; ++t) s_Pt[t * PS + r] = a[t];   // transposed
        }
        __syncthreads();

        // D: warp0 = forward-substitution solver; warps 1-15 = SYRK
        if (wid == 0) {
            // z-block solve: L11 z = b (both RHS packed)
            u64 a = s_bp[k0 + lane];
            for (int t = 0; t < 32; ++t) {
                u64 vt = __shfl_sync(0xffffffffu, a, t);
                u64 v  = fmul2(vt, splat2(s_inv[t]));
                if (lane == t) s_bp[k0 + t] = v;
                float l = s_D[lane * 33 + t];
                if (lane > t) ffma2(a, nsplat2(l), v);
            }
            __syncwarp();
            // trailing b -= L21 * z (panel in shared)
            for (int r = lane; r < M; r += 32) {
                u64 bp = s_bp[k0 + 32 + r];
#pragma unroll 8
                for (int t = 0; t < 32; ++t)
                    ffma2(bp, nsplat2(s_Pt[t * PS + r]), s_bp[k0 + t]);
                s_bp[k0 + 32 + r] = bp;
            }
        } else if (M > 0) {
            // SYRK: A22 -= P P^T  (64x32 tiles, packed f32x2 math)
            int wslot = wid - 1;
            int RT = (M + 63) >> 6;
            int CT = M >> 5;
            int cnt = 0;
            for (int bi = 0; bi < RT; ++bi) {
                int bjmax = min(2 * bi + 1, CT - 1);
                for (int bj = 0; bj <= bjmax; ++bj) {
                    if (cnt == wslot) {
                        int r1 = bi * 64 + lane, r2 = r1 + 32;
                        int cb = bj * 32;
                        bool v1 = r1 < M, v2 = r2 < M;
                        u64 acc0[16], acc1[16];
#pragma unroll
                        for (int c = 0; c < 16; ++c) { acc0[c] = 0ull; acc1[c] = 0ull; }
#pragma unroll 8
                        for (int t = 0; t < 32; ++t) {
                            float a0 = v1 ? s_Pt[t * PS + r1] : 0.f;
                            float a1 = v2 ? s_Pt[t * PS + r2] : 0.f;
                            u64 na0 = nsplat2(a0), na1 = nsplat2(a1);
                            const double2* pp = (const double2*)(s_Pt + t * PS + cb);
#pragma unroll
                            for (int c = 0; c < 8; ++c) {
                                double2 p = pp[c];
                                u64 pl = __double_as_longlong(p.x);
                                u64 ph = __double_as_longlong(p.y);
                                ffma2(acc0[2 * c],     na0, pl);
                                ffma2(acc0[2 * c + 1], na0, ph);
                                ffma2(acc1[2 * c],     na1, pl);
                                ffma2(acc1[2 * c + 1], na1, ph);
                            }
                        }
                        if (v1) {
                            double2* cp = (double2*)(C + (size_t)(k0 + 32 + r1) * NA + k0 + 32 + cb);
#pragma unroll
                            for (int c = 0; c < 8; ++c) {
                                double2 v = cp[c];
                                v.x = __longlong_as_double(fadd2(__double_as_longlong(v.x), acc0[2 * c]));
                                v.y = __longlong_as_double(fadd2(__double_as_longlong(v.y), acc0[2 * c + 1]));
                                cp[c] = v;
                            }
                        }
                        if (v2) {
                            double2* cp = (double2*)(C + (size_t)(k0 + 32 + r2) * NA + k0 + 32 + cb);
#pragma unroll
                            for (int c = 0; c < 8; ++c) {
                                double2 v = cp[c];
                                v.x = __longlong_as_double(fadd2(__double_as_longlong(v.x), acc1[2 * c]));
                                v.y = __longlong_as_double(fadd2(__double_as_longlong(v.y), acc1[2 * c + 1]));
                                cp[c] = v;
                            }
                        }
                    }
                    if (++cnt == 15) cnt = 0;
                }
            }
        }
        __syncthreads();
    }

    // =================== backward: L^T y = z ================================
    for (int kb = NA / 32 - 1; kb >= 0; --kb) {
        int k0 = kb * 32;
        if (wid == 0) {
            for (int e = lane; e < 1024; e += 32) {
                int i = e >> 5, j = e & 31;
                s_D[i * 33 + j] = C[(size_t)(k0 + i) * NA + k0 + j];
            }
            __syncwarp();
            u64 a = s_bp[k0 + lane];
            for (int t = 31; t >= 0; --t) {
                u64 vt = __shfl_sync(0xffffffffu, a, t);
                u64 v  = fmul2(vt, splat2(s_invall[k0 + t]));
                if (lane == t) s_bp[k0 + t] = v;
                float l = s_D[t * 33 + lane];
                if (lane < t) ffma2(a, nsplat2(l), v);
            }
        }
        __syncthreads();
        for (int j = tid; j < k0; j += 512) {
            u64 bp = s_bp[j];
#pragma unroll
            for (int t = 0; t < 32; ++t)
                ffma2(bp, nsplat2(C[(size_t)(k0 + t) * NA + j]), s_bp[k0 + t]);
            s_bp[j] = bp;
        }
        __syncthreads();
    }

    // =================== lambda, q, energy ==================================
    float y0, y1;
    unpack2(s_bp[tid], y0, y1);
    float l0 = y0, l1 = y1;
#pragma unroll
    for (int off = 16; off; off >>= 1) {
        l0 += __shfl_down_sync(0xffffffffu, l0, off);
        l1 += __shfl_down_sync(0xffffffffu, l1, off);
    }
    if (lane == 0) { s_red[wid] = l0; s_red[32 + wid] = l1; }
    __syncthreads();
    if (tid == 0) {
        float S1 = 0.f, S2 = 0.f;
        for (int w = 0; w < 16; ++w) { S1 += s_red[w]; S2 += s_red[32 + w]; }
        *s_lam = (S1 - tc[m]) / S2;
    }
    __syncthreads();
    float lam = *s_lam;

    float q = y0 - lam * y1;
    out[NB_MOL + m * NA + tid] = q;

    // e = 0.5 * (chi.q - lam * Q)   [exact KKT identity]
    float ep = g_chi[m * NA + tid] * q;
#pragma unroll
    for (int off = 16; off; off >>= 1) ep += __shfl_down_sync(0xffffffffu, ep, off);
    if (lane == 0) s_red[wid] = ep;
    __syncthreads();
    if (tid == 0) {
        float s = 0.f;
        for (int w = 0; w < 16; ++w) s += s_red[w];
        out[m] = 0.5f * (s - lam * tc[m]);
    }
}

// ---------------- launch ----------------------------------------------------
extern "C" void kernel_launch(void* const* d_in, const int* in_sizes, int n_in,
                              void* d_out, int out_size) {
    const float* feats = (const float*)d_in[0];   // (N, 64)
    const float* pos   = (const float*)d_in[1];   // (N, 3)
    const int*   atype = (const int*)  d_in[2];   // (N,)
    const float* tc    = (const float*)d_in[3];   // (B, 1)
    const float* w     = (const float*)d_in[4];   // (64, 1)
    const float* hard  = (const float*)d_in[5];   // (4,)
    const float* sigma = (const float*)d_in[6];   // (4,)
    float* out = (float*)d_out;                   // [B e | N q]

    (void)in_sizes; (void)n_in; (void)out_size;

    chi_kernel<<<NB_MOL * NA / 8, 256>>>(feats, w);
    build_kernel<<<dim3(16, NB_MOL), 256>>>(pos, atype, hard, sigma);
    cudaFuncSetAttribute(fact_solve_kernel, cudaFuncAttributeMaxDynamicSharedMemorySize, CHO_SHMEM);
    fact_solve_kernel<<<NB_MOL, 512, CHO_SHMEM>>>(tc, out);
}